// round 2
// baseline (speedup 1.0000x reference)
#include <cuda_runtime.h>
#include <math.h>

#define BATCH 8
#define C1    192
#define C3    576
#define HEADS 4
#define CHD   48
#define HH    128
#define WW    128
#define NPIX  16384
#define EPSV  1e-5f

// ---------------- scratch (static device allocations; no cudaMalloc) --------
__device__ float g_bufA[BATCH * C3 * NPIX];   // 576-ch scratch (302 MB)
__device__ float g_bufB[BATCH * C3 * NPIX];   // 576-ch scratch (302 MB)
__device__ float g_bufC[BATCH * C1 * NPIX];   // 192-ch scratch (100 MB)
__device__ float g_bufD[BATCH * C1 * NPIX];   // 192-ch scratch (100 MB)
__device__ float g_sumsq[BATCH * 2 * C1];     // q/k row sum-of-squares (rows 0..383 per batch)
__device__ float g_attn_part[32 * 16 * CHD * CHD];
__device__ float g_attn[32 * CHD * CHD];

// ---------------- LayerNorm over channel dim (per pixel) --------------------
__global__ void __launch_bounds__(256) ln_kernel(
    const float* __restrict__ x, float* __restrict__ out,
    const float* __restrict__ w, const float* __restrict__ b)
{
    int idx = blockIdx.x * 256 + threadIdx.x;      // over BATCH*NPIX
    int bb = idx >> 14;
    int p  = idx & (NPIX - 1);
    const float* xp = x + (size_t)bb * C1 * NPIX + p;
    float s = 0.f, s2 = 0.f;
    #pragma unroll 4
    for (int c = 0; c < C1; c++) {
        float v = xp[(size_t)c * NPIX];
        s += v; s2 = fmaf(v, v, s2);
    }
    float mu  = s * (1.f / C1);
    float var = fmaxf(s2 * (1.f / C1) - mu * mu, 0.f);
    float inv = rsqrtf(var + EPSV);
    float* op = out + (size_t)bb * C1 * NPIX + p;
    #pragma unroll 4
    for (int c = 0; c < C1; c++) {
        op[(size_t)c * NPIX] = (xp[(size_t)c * NPIX] - mu) * inv * w[c] + b[c];
    }
}

// ---------------- 1x1 conv = GEMM  (out[oc,p] = sum_ic W[oc,ic]*in[ic,p]+b) -
// FUSE: 0 = bias only, 1 = bias+GELU(exact), 2 = bias+residual
template<int CIN, int FUSE>
__global__ void __launch_bounds__(256) pwconv_kernel(
    const float* __restrict__ in, float* __restrict__ out,
    const float* __restrict__ Wt, const float* __restrict__ bias,
    const float* __restrict__ resid, int COUT)
{
    __shared__ float  sW[16][64];
    __shared__ float4 sI[16][64];   // 16 ic x 256 px
    const int tid = threadIdx.x;
    const int p0  = blockIdx.x * 256;
    const int ocb = blockIdx.y * 64;
    const int bb  = blockIdx.z;
    const float* inb = in + (size_t)bb * CIN * NPIX + p0;
    const int tx = tid & 31, ty = tid >> 5;

    float acc[8][8];
    #pragma unroll
    for (int m = 0; m < 8; m++)
        #pragma unroll
        for (int j = 0; j < 8; j++) acc[m][j] = 0.f;

    for (int k0 = 0; k0 < CIN; k0 += 16) {
        #pragma unroll
        for (int i = tid; i < 1024; i += 256) {
            int oc = i >> 4, kk = i & 15;
            sW[kk][oc] = Wt[(size_t)(ocb + oc) * CIN + k0 + kk];
        }
        #pragma unroll
        for (int i = tid; i < 1024; i += 256) {
            int kk = i >> 6, q = i & 63;
            sI[kk][q] = *(const float4*)(inb + (size_t)(k0 + kk) * NPIX + q * 4);
        }
        __syncthreads();
        #pragma unroll
        for (int kk = 0; kk < 16; kk++) {
            float4 b0 = sI[kk][tx];
            float4 b1 = sI[kk][tx + 32];
            #pragma unroll
            for (int m = 0; m < 8; m++) {
                float a = sW[kk][ty * 8 + m];
                acc[m][0] = fmaf(a, b0.x, acc[m][0]);
                acc[m][1] = fmaf(a, b0.y, acc[m][1]);
                acc[m][2] = fmaf(a, b0.z, acc[m][2]);
                acc[m][3] = fmaf(a, b0.w, acc[m][3]);
                acc[m][4] = fmaf(a, b1.x, acc[m][4]);
                acc[m][5] = fmaf(a, b1.y, acc[m][5]);
                acc[m][6] = fmaf(a, b1.z, acc[m][6]);
                acc[m][7] = fmaf(a, b1.w, acc[m][7]);
            }
        }
        __syncthreads();
    }

    #pragma unroll
    for (int m = 0; m < 8; m++) {
        int oc = ocb + ty * 8 + m;
        float bv = bias[oc];
        float* orow = out + ((size_t)bb * COUT + oc) * NPIX;
        float v[8];
        #pragma unroll
        for (int j = 0; j < 8; j++) {
            float t = acc[m][j] + bv;
            if (FUSE == 1) t = 0.5f * t * (1.f + erff(t * 0.70710678118654752f));
            v[j] = t;
        }
        if (FUSE == 2) {
            const float* rrow = resid + ((size_t)bb * COUT + oc) * NPIX;
            float4 r0 = *(const float4*)(rrow + p0 + tx * 4);
            float4 r1 = *(const float4*)(rrow + p0 + 128 + tx * 4);
            v[0] += r0.x; v[1] += r0.y; v[2] += r0.z; v[3] += r0.w;
            v[4] += r1.x; v[5] += r1.y; v[6] += r1.z; v[7] += r1.w;
        }
        *(float4*)(orow + p0 + tx * 4)       = make_float4(v[0], v[1], v[2], v[3]);
        *(float4*)(orow + p0 + 128 + tx * 4) = make_float4(v[4], v[5], v[6], v[7]);
    }
}

// ---------------- depthwise / grouped 3x3 conv, pad 1 -----------------------
// RATIO: out channels per input channel (1 = depthwise 576->576, 3 = 192->576)
// prompt != nullptr fuses the attention prompt add as an extra per-channel bias
template<int RATIO>
__global__ void __launch_bounds__(256) dwconv_kernel(
    const float* __restrict__ in, float* __restrict__ out,
    const float* __restrict__ wt, const float* __restrict__ bias,
    const float* __restrict__ prompt)
{
    int idx = blockIdx.x * 256 + threadIdx.x;     // over BATCH*C3*NPIX
    int p    = idx & (NPIX - 1);
    int rest = idx >> 14;
    int c    = rest % C3;
    int bb   = rest / C3;
    int y = p >> 7, xc = p & (WW - 1);

    const float* ip = in + ((size_t)bb * (C3 / RATIO) + c / RATIO) * NPIX;
    const float* wp = wt + c * 9;
    float acc = bias[c];
    if (prompt != nullptr)
        acc += prompt[((c % C1) / CHD) * CHD + (c % CHD)];

    #pragma unroll
    for (int dy = -1; dy <= 1; dy++) {
        int yy = y + dy;
        if ((unsigned)yy < (unsigned)HH) {
            const float* rp = ip + yy * WW;
            #pragma unroll
            for (int dx = -1; dx <= 1; dx++) {
                int xx = xc + dx;
                if ((unsigned)xx < (unsigned)WW)
                    acc = fmaf(__ldg(&wp[(dy + 1) * 3 + (dx + 1)]), rp[xx], acc);
            }
        }
    }
    out[idx] = acc;   // idx == ((bb*C3 + c)*NPIX + p)
}

// ---------------- sum of squares per (b, q/k channel) row -------------------
__global__ void __launch_bounds__(256) sumsq_kernel(const float* __restrict__ qkv)
{
    int row = blockIdx.x;              // 0 .. 8*384-1
    int bb = row / 384;
    int r  = row - bb * 384;           // q: 0..191, k: 192..383 (channel in qkv)
    const float* p = qkv + ((size_t)bb * C3 + r) * NPIX;
    float s = 0.f;
    for (int i = threadIdx.x; i < NPIX; i += 256) {
        float v = p[i];
        s = fmaf(v, v, s);
    }
    __shared__ float red[8];
    #pragma unroll
    for (int off = 16; off > 0; off >>= 1)
        s += __shfl_down_sync(0xffffffffu, s, off);
    if ((threadIdx.x & 31) == 0) red[threadIdx.x >> 5] = s;
    __syncthreads();
    if (threadIdx.x == 0) {
        float t = 0.f;
        #pragma unroll
        for (int wv = 0; wv < 8; wv++) t += red[wv];
        g_sumsq[row] = t;
    }
}

// ---------------- QK^T partial GEMM (48x48, split-K over spatial) -----------
__global__ void __launch_bounds__(256) qk_partial_kernel(const float* __restrict__ qkv)
{
    const int bh = blockIdx.x, split = blockIdx.y;
    const int bb = bh >> 2, h = bh & 3;
    const float* qb = qkv + ((size_t)bb * C3 + h * CHD) * NPIX + split * 1024;
    const float* kb = qkv + ((size_t)bb * C3 + C1 + h * CHD) * NPIX + split * 1024;
    __shared__ float sq[CHD][33];
    __shared__ float sk[CHD][33];
    const int tid = threadIdx.x;
    const int c0 = (tid >> 4) * 3, d0 = (tid & 15) * 3;
    float acc[3][3] = {};

    for (int n0 = 0; n0 < 1024; n0 += 32) {
        for (int i = tid; i < CHD * 32; i += 256) {
            int c = i >> 5, j = i & 31;
            sq[c][j] = qb[(size_t)c * NPIX + n0 + j];
            sk[c][j] = kb[(size_t)c * NPIX + n0 + j];
        }
        __syncthreads();
        #pragma unroll
        for (int j = 0; j < 32; j++) {
            float q0 = sq[c0][j], q1 = sq[c0 + 1][j], q2 = sq[c0 + 2][j];
            float k0v = sk[d0][j], k1v = sk[d0 + 1][j], k2v = sk[d0 + 2][j];
            acc[0][0] = fmaf(q0, k0v, acc[0][0]);
            acc[0][1] = fmaf(q0, k1v, acc[0][1]);
            acc[0][2] = fmaf(q0, k2v, acc[0][2]);
            acc[1][0] = fmaf(q1, k0v, acc[1][0]);
            acc[1][1] = fmaf(q1, k1v, acc[1][1]);
            acc[1][2] = fmaf(q1, k2v, acc[1][2]);
            acc[2][0] = fmaf(q2, k0v, acc[2][0]);
            acc[2][1] = fmaf(q2, k1v, acc[2][1]);
            acc[2][2] = fmaf(q2, k2v, acc[2][2]);
        }
        __syncthreads();
    }
    float* op = g_attn_part + ((size_t)bh * 16 + split) * CHD * CHD;
    #pragma unroll
    for (int a = 0; a < 3; a++)
        #pragma unroll
        for (int e = 0; e < 3; e++)
            op[(c0 + a) * CHD + d0 + e] = acc[a][e];
}

// ---------------- reduce partials + normalize + temperature + softmax -------
__global__ void __launch_bounds__(256) attn_softmax_kernel(const float* __restrict__ temp)
{
    const int bh = blockIdx.x;
    const int bb = bh >> 2, h = bh & 3;
    __shared__ float sA[CHD * CHD];
    const int tid = threadIdx.x;
    const float tpr = temp[h];
    for (int i = tid; i < CHD * CHD; i += 256) {
        float s = 0.f;
        #pragma unroll
        for (int sp = 0; sp < 16; sp++)
            s += g_attn_part[((size_t)bh * 16 + sp) * CHD * CHD + i];
        int c = i / CHD, d = i - c * CHD;
        float nq = fmaxf(sqrtf(g_sumsq[bb * 384 + h * CHD + c]), 1e-12f);
        float nk = fmaxf(sqrtf(g_sumsq[bb * 384 + C1 + h * CHD + d]), 1e-12f);
        sA[i] = s / (nq * nk) * tpr;
    }
    __syncthreads();
    if (tid < CHD) {
        float mx = -1e30f;
        #pragma unroll
        for (int d = 0; d < CHD; d++) mx = fmaxf(mx, sA[tid * CHD + d]);
        float e[CHD];
        float ssum = 0.f;
        #pragma unroll
        for (int d = 0; d < CHD; d++) {
            e[d] = expf(sA[tid * CHD + d] - mx);
            ssum += e[d];
        }
        float inv = 1.f / ssum;
        #pragma unroll
        for (int d = 0; d < CHD; d++)
            g_attn[(size_t)bh * CHD * CHD + tid * CHD + d] = e[d] * inv;
    }
}

// ---------------- out = attn @ v  (per (b,h): 48x16384, K=48) ---------------
__global__ void __launch_bounds__(256) attnv_kernel(
    const float* __restrict__ qkv, float* __restrict__ out)
{
    const int bh = blockIdx.y;
    const int bb = bh >> 2, h = bh & 3;
    const int p = blockIdx.x * 256 + threadIdx.x;
    __shared__ float sA[CHD * CHD];
    for (int i = threadIdx.x; i < CHD * CHD; i += 256)
        sA[i] = g_attn[(size_t)bh * CHD * CHD + i];
    __syncthreads();
    const float* vb = qkv + ((size_t)bb * C3 + 2 * C1 + h * CHD) * NPIX + p;
    float vv[CHD];
    #pragma unroll
    for (int d = 0; d < CHD; d++) vv[d] = vb[(size_t)d * NPIX];
    float* ob = out + ((size_t)bb * C1 + h * CHD) * NPIX + p;
    for (int c = 0; c < CHD; c++) {
        float a = 0.f;
        #pragma unroll
        for (int d = 0; d < CHD; d++) a = fmaf(sA[c * CHD + d], vv[d], a);
        ob[(size_t)c * NPIX] = a;
    }
}

// ---------------- launch ----------------------------------------------------
extern "C" void kernel_launch(void* const* d_in, const int* in_sizes, int n_in,
                              void* d_out, int out_size)
{
    const float* x       = (const float*)d_in[0];
    const float* ln1_w   = (const float*)d_in[1];
    const float* ln1_b   = (const float*)d_in[2];
    const float* qkv_w   = (const float*)d_in[3];
    const float* qkv_b   = (const float*)d_in[4];
    const float* qkv_dww = (const float*)d_in[5];
    const float* qkv_dwb = (const float*)d_in[6];
    const float* temp    = (const float*)d_in[7];
    const float* prompt  = (const float*)d_in[8];
    const float* proj_w  = (const float*)d_in[9];
    const float* proj_b  = (const float*)d_in[10];
    const float* ln2_w   = (const float*)d_in[11];
    const float* ln2_b   = (const float*)d_in[12];
    const float* dw1_w   = (const float*)d_in[13];
    const float* dw1_b   = (const float*)d_in[14];
    const float* pm_w    = (const float*)d_in[15];
    const float* pm_b    = (const float*)d_in[16];
    const float* dw2_w   = (const float*)d_in[17];
    const float* dw2_b   = (const float*)d_in[18];
    const float* po_w    = (const float*)d_in[19];
    const float* po_b    = (const float*)d_in[20];
    float* out = (float*)d_out;

    void *pA, *pB, *pC, *pD;
    cudaGetSymbolAddress(&pA, g_bufA);
    cudaGetSymbolAddress(&pB, g_bufB);
    cudaGetSymbolAddress(&pC, g_bufC);
    cudaGetSymbolAddress(&pD, g_bufD);
    float* bufA = (float*)pA;
    float* bufB = (float*)pB;
    float* bufC = (float*)pC;
    float* bufD = (float*)pD;

    const int dwGrid = BATCH * C3 * NPIX / 256;   // 294912

    // ---- attention branch ----
    ln_kernel<<<BATCH * NPIX / 256, 256>>>(x, bufC, ln1_w, ln1_b);
    pwconv_kernel<C1, 0><<<dim3(NPIX / 256, C3 / 64, BATCH), 256>>>(
        bufC, bufA, qkv_w, qkv_b, nullptr, C3);
    dwconv_kernel<1><<<dwGrid, 256>>>(bufA, bufB, qkv_dww, qkv_dwb, prompt);
    sumsq_kernel<<<BATCH * 384, 256>>>(bufB);
    qk_partial_kernel<<<dim3(32, 16), 256>>>(bufB);
    attn_softmax_kernel<<<32, 256>>>(temp);
    attnv_kernel<<<dim3(NPIX / 256, 32), 256>>>(bufB, bufC);
    pwconv_kernel<C1, 2><<<dim3(NPIX / 256, C1 / 64, BATCH), 256>>>(
        bufC, bufD, proj_w, proj_b, x, C1);           // y1 = x + proj(attn_out)

    // ---- FFN branch ----
    ln_kernel<<<BATCH * NPIX / 256, 256>>>(bufD, bufC, ln2_w, ln2_b);
    dwconv_kernel<3><<<dwGrid, 256>>>(bufC, bufA, dw1_w, dw1_b, nullptr);
    pwconv_kernel<C3, 1><<<dim3(NPIX / 256, C3 / 64, BATCH), 256>>>(
        bufA, bufB, pm_w, pm_b, nullptr, C3);         // + GELU
    dwconv_kernel<1><<<dwGrid, 256>>>(bufB, bufA, dw2_w, dw2_b, nullptr);
    pwconv_kernel<C3, 2><<<dim3(NPIX / 256, C1 / 64, BATCH), 256>>>(
        bufA, out, po_w, po_b, bufD, C1);             // out = y1 + po(...)
}

// round 3
// speedup vs baseline: 1.6192x; 1.6192x over previous
#include <cuda_runtime.h>
#include <math.h>
#include <stdint.h>

#define BATCH 8
#define C1    192
#define C3    576
#define HEADS 4
#define CHD   48
#define HH    128
#define WW    128
#define NPIX  16384
#define EPSV  1e-5f

// ---------------- scratch (static device allocations; no cudaMalloc) --------
__device__ float g_bufA[BATCH * C3 * NPIX];
__device__ float g_bufB[BATCH * C3 * NPIX];
__device__ float g_bufC[BATCH * C1 * NPIX];
__device__ float g_bufD[BATCH * C1 * NPIX];
__device__ float g_sumsq[BATCH * 2 * C1];
__device__ float g_attn_part[32 * 16 * CHD * CHD];
__device__ float g_attn[32 * CHD * CHD];

// ---------------- LayerNorm over channel dim (per pixel) --------------------
__global__ void __launch_bounds__(256) ln_kernel(
    const float* __restrict__ x, float* __restrict__ out,
    const float* __restrict__ w, const float* __restrict__ b)
{
    int idx = blockIdx.x * 256 + threadIdx.x;
    int bb = idx >> 14;
    int p  = idx & (NPIX - 1);
    const float* xp = x + (size_t)bb * C1 * NPIX + p;
    float s = 0.f, s2 = 0.f;
    #pragma unroll 4
    for (int c = 0; c < C1; c++) {
        float v = xp[(size_t)c * NPIX];
        s += v; s2 = fmaf(v, v, s2);
    }
    float mu  = s * (1.f / C1);
    float var = fmaxf(s2 * (1.f / C1) - mu * mu, 0.f);
    float inv = rsqrtf(var + EPSV);
    float* op = out + (size_t)bb * C1 * NPIX + p;
    #pragma unroll 4
    for (int c = 0; c < C1; c++) {
        op[(size_t)c * NPIX] = (xp[(size_t)c * NPIX] - mu) * inv * w[c] + b[c];
    }
}

// ---------------- tf32 tensor-core GEMM for 1x1 convs -----------------------
// out[oc,p] = sum_ic W[oc,ic] * in[ic,p]  (+bias, +fuse)
// FUSE: 0 = bias, 1 = bias+GELU(exact), 2 = bias+residual
// CTA tile: 64(M) x 256(N), BK=32. 8 warps, each 64x32 (4 m16 x 4 n8 mma tiles).
__device__ __forceinline__ uint32_t f2tf(float f) {
    uint32_t u; asm("cvt.rna.tf32.f32 %0, %1;" : "=r"(u) : "f"(f)); return u;
}
__device__ __forceinline__ void mma_tf32(float* c, const uint32_t* a, const uint32_t* b) {
    asm volatile(
        "mma.sync.aligned.m16n8k8.row.col.f32.tf32.tf32.f32 "
        "{%0,%1,%2,%3}, {%4,%5,%6,%7}, {%8,%9}, {%0,%1,%2,%3};\n"
        : "+f"(c[0]), "+f"(c[1]), "+f"(c[2]), "+f"(c[3])
        : "r"(a[0]), "r"(a[1]), "r"(a[2]), "r"(a[3]), "r"(b[0]), "r"(b[1]));
}
// A smem swizzle: XOR m bits[3:4] with k bits[3:4] so both STS (k-contig per
// thread) and LDS (m-contig per quad) hit 32 distinct banks (stride 72 = 8 mod 32).
#define SA_IDX(k, m) ((m) ^ ((((k) >> 3) & 3) << 3))

template<int FUSE>
__global__ void __launch_bounds__(256) gemm_tf32_kernel(
    const float* __restrict__ in, float* __restrict__ out,
    const float* __restrict__ W, const float* __restrict__ bias,
    const float* __restrict__ resid, int M, int K)
{
    __shared__ uint32_t As[32][72];    // [k][m-swizzled], 64 m + pad
    __shared__ uint32_t Bs[32][264];   // [k][n], 256 n + pad 8

    const int tid  = threadIdx.x;
    const int lane = tid & 31;
    const int wrp  = tid >> 5;
    const int n0   = blockIdx.x * 256;
    const int m0   = blockIdx.y * 64;
    const int bb   = blockIdx.z;
    const float* inb = in + (size_t)bb * K * NPIX + n0;

    float acc[4][4][4];
    #pragma unroll
    for (int mt = 0; mt < 4; mt++)
        #pragma unroll
        for (int nt = 0; nt < 4; nt++)
            #pragma unroll
            for (int i = 0; i < 4; i++) acc[mt][nt][i] = 0.f;

    const int am = tid >> 2;          // A row (m) 0..63
    const int ak = (tid & 3) * 8;     // A col (k) base

    for (int k0 = 0; k0 < K; k0 += 32) {
        // A tile: W[m0+am][k0+ak .. +8]
        {
            const float* wr = W + (size_t)(m0 + am) * K + k0 + ak;
            float4 w0 = *(const float4*)wr;
            float4 w1 = *(const float4*)(wr + 4);
            As[ak + 0][SA_IDX(ak + 0, am)] = f2tf(w0.x);
            As[ak + 1][SA_IDX(ak + 1, am)] = f2tf(w0.y);
            As[ak + 2][SA_IDX(ak + 2, am)] = f2tf(w0.z);
            As[ak + 3][SA_IDX(ak + 3, am)] = f2tf(w0.w);
            As[ak + 4][SA_IDX(ak + 4, am)] = f2tf(w1.x);
            As[ak + 5][SA_IDX(ak + 5, am)] = f2tf(w1.y);
            As[ak + 6][SA_IDX(ak + 6, am)] = f2tf(w1.z);
            As[ak + 7][SA_IDX(ak + 7, am)] = f2tf(w1.w);
        }
        // B tile: in[k0+r][n0 .. +256]
        #pragma unroll
        for (int i = 0; i < 8; i++) {
            int l  = tid + i * 256;        // 0..2047 float4 slots
            int r  = l >> 6;
            int c4 = (l & 63) * 4;
            float4 v = *(const float4*)(inb + (size_t)(k0 + r) * NPIX + c4);
            uint4 t;
            t.x = f2tf(v.x); t.y = f2tf(v.y); t.z = f2tf(v.z); t.w = f2tf(v.w);
            *(uint4*)&Bs[r][c4] = t;
        }
        __syncthreads();

        #pragma unroll
        for (int kk = 0; kk < 32; kk += 8) {
            const int kr   = kk + (lane & 3);
            const int mrow = lane >> 2;
            const int xc   = ((kk >> 3) & 3) << 3;   // swizzle const this k8
            uint32_t a[4][4], b[4][2];
            #pragma unroll
            for (int mt = 0; mt < 4; mt++) {
                int mb = mt * 16 + mrow;
                a[mt][0] = As[kr    ][(mb    ) ^ xc];
                a[mt][1] = As[kr    ][(mb + 8) ^ xc];
                a[mt][2] = As[kr + 4][(mb    ) ^ xc];
                a[mt][3] = As[kr + 4][(mb + 8) ^ xc];
            }
            #pragma unroll
            for (int nt = 0; nt < 4; nt++) {
                int nc = wrp * 32 + nt * 8 + (lane >> 2);
                b[nt][0] = Bs[kr    ][nc];
                b[nt][1] = Bs[kr + 4][nc];
            }
            #pragma unroll
            for (int mt = 0; mt < 4; mt++)
                #pragma unroll
                for (int nt = 0; nt < 4; nt++)
                    mma_tf32(acc[mt][nt], a[mt], b[nt]);
        }
        __syncthreads();
    }

    // epilogue
    #pragma unroll
    for (int mt = 0; mt < 4; mt++) {
        int r0 = m0 + mt * 16 + (lane >> 2);
        int r1 = r0 + 8;
        float bv0 = __ldg(&bias[r0]);
        float bv1 = __ldg(&bias[r1]);
        float* o0 = out + ((size_t)bb * M + r0) * NPIX + n0;
        float* o1 = out + ((size_t)bb * M + r1) * NPIX + n0;
        #pragma unroll
        for (int nt = 0; nt < 4; nt++) {
            int col = wrp * 32 + nt * 8 + (lane & 3) * 2;
            float v0 = acc[mt][nt][0] + bv0;
            float v1 = acc[mt][nt][1] + bv0;
            float v2 = acc[mt][nt][2] + bv1;
            float v3 = acc[mt][nt][3] + bv1;
            if (FUSE == 1) {
                v0 = 0.5f * v0 * (1.f + erff(v0 * 0.70710678118654752f));
                v1 = 0.5f * v1 * (1.f + erff(v1 * 0.70710678118654752f));
                v2 = 0.5f * v2 * (1.f + erff(v2 * 0.70710678118654752f));
                v3 = 0.5f * v3 * (1.f + erff(v3 * 0.70710678118654752f));
            }
            if (FUSE == 2) {
                const float* rr0 = resid + ((size_t)bb * M + r0) * NPIX + n0;
                const float* rr1 = resid + ((size_t)bb * M + r1) * NPIX + n0;
                float2 q0 = *(const float2*)(rr0 + col);
                float2 q1 = *(const float2*)(rr1 + col);
                v0 += q0.x; v1 += q0.y; v2 += q1.x; v3 += q1.y;
            }
            *(float2*)(o0 + col) = make_float2(v0, v1);
            *(float2*)(o1 + col) = make_float2(v2, v3);
        }
    }
}

// ---------------- depthwise / grouped 3x3 conv, pad 1 -----------------------
template<int RATIO>
__global__ void __launch_bounds__(256) dwconv_kernel(
    const float* __restrict__ in, float* __restrict__ out,
    const float* __restrict__ wt, const float* __restrict__ bias,
    const float* __restrict__ prompt)
{
    int idx = blockIdx.x * 256 + threadIdx.x;
    int p    = idx & (NPIX - 1);
    int rest = idx >> 14;
    int c    = rest % C3;
    int bb   = rest / C3;
    int y = p >> 7, xc = p & (WW - 1);

    const float* ip = in + ((size_t)bb * (C3 / RATIO) + c / RATIO) * NPIX;
    const float* wp = wt + c * 9;
    float acc = bias[c];
    if (prompt != nullptr)
        acc += prompt[((c % C1) / CHD) * CHD + (c % CHD)];

    #pragma unroll
    for (int dy = -1; dy <= 1; dy++) {
        int yy = y + dy;
        if ((unsigned)yy < (unsigned)HH) {
            const float* rp = ip + yy * WW;
            #pragma unroll
            for (int dx = -1; dx <= 1; dx++) {
                int xx = xc + dx;
                if ((unsigned)xx < (unsigned)WW)
                    acc = fmaf(__ldg(&wp[(dy + 1) * 3 + (dx + 1)]), rp[xx], acc);
            }
        }
    }
    out[idx] = acc;
}

// ---------------- sum of squares per (b, q/k channel) row -------------------
__global__ void __launch_bounds__(256) sumsq_kernel(const float* __restrict__ qkv)
{
    int row = blockIdx.x;
    int bb = row / 384;
    int r  = row - bb * 384;
    const float* p = qkv + ((size_t)bb * C3 + r) * NPIX;
    float s = 0.f;
    for (int i = threadIdx.x; i < NPIX; i += 256) {
        float v = p[i];
        s = fmaf(v, v, s);
    }
    __shared__ float red[8];
    #pragma unroll
    for (int off = 16; off > 0; off >>= 1)
        s += __shfl_down_sync(0xffffffffu, s, off);
    if ((threadIdx.x & 31) == 0) red[threadIdx.x >> 5] = s;
    __syncthreads();
    if (threadIdx.x == 0) {
        float t = 0.f;
        #pragma unroll
        for (int wv = 0; wv < 8; wv++) t += red[wv];
        g_sumsq[row] = t;
    }
}

// ---------------- QK^T partial GEMM (48x48, split-K over spatial) -----------
__global__ void __launch_bounds__(256) qk_partial_kernel(const float* __restrict__ qkv)
{
    const int bh = blockIdx.x, split = blockIdx.y;
    const int bb = bh >> 2, h = bh & 3;
    const float* qb = qkv + ((size_t)bb * C3 + h * CHD) * NPIX + split * 1024;
    const float* kb = qkv + ((size_t)bb * C3 + C1 + h * CHD) * NPIX + split * 1024;
    __shared__ float sq[CHD][33];
    __shared__ float sk[CHD][33];
    const int tid = threadIdx.x;
    const int c0 = (tid >> 4) * 3, d0 = (tid & 15) * 3;
    float acc[3][3] = {};

    for (int n0 = 0; n0 < 1024; n0 += 32) {
        for (int i = tid; i < CHD * 32; i += 256) {
            int c = i >> 5, j = i & 31;
            sq[c][j] = qb[(size_t)c * NPIX + n0 + j];
            sk[c][j] = kb[(size_t)c * NPIX + n0 + j];
        }
        __syncthreads();
        #pragma unroll
        for (int j = 0; j < 32; j++) {
            float q0 = sq[c0][j], q1 = sq[c0 + 1][j], q2 = sq[c0 + 2][j];
            float k0v = sk[d0][j], k1v = sk[d0 + 1][j], k2v = sk[d0 + 2][j];
            acc[0][0] = fmaf(q0, k0v, acc[0][0]);
            acc[0][1] = fmaf(q0, k1v, acc[0][1]);
            acc[0][2] = fmaf(q0, k2v, acc[0][2]);
            acc[1][0] = fmaf(q1, k0v, acc[1][0]);
            acc[1][1] = fmaf(q1, k1v, acc[1][1]);
            acc[1][2] = fmaf(q1, k2v, acc[1][2]);
            acc[2][0] = fmaf(q2, k0v, acc[2][0]);
            acc[2][1] = fmaf(q2, k1v, acc[2][1]);
            acc[2][2] = fmaf(q2, k2v, acc[2][2]);
        }
        __syncthreads();
    }
    float* op = g_attn_part + ((size_t)bh * 16 + split) * CHD * CHD;
    #pragma unroll
    for (int a = 0; a < 3; a++)
        #pragma unroll
        for (int e = 0; e < 3; e++)
            op[(c0 + a) * CHD + d0 + e] = acc[a][e];
}

// ---------------- reduce partials + normalize + temperature + softmax -------
__global__ void __launch_bounds__(256) attn_softmax_kernel(const float* __restrict__ temp)
{
    const int bh = blockIdx.x;
    const int bb = bh >> 2, h = bh & 3;
    __shared__ float sA[CHD * CHD];
    const int tid = threadIdx.x;
    const float tpr = temp[h];
    for (int i = tid; i < CHD * CHD; i += 256) {
        float s = 0.f;
        #pragma unroll
        for (int sp = 0; sp < 16; sp++)
            s += g_attn_part[((size_t)bh * 16 + sp) * CHD * CHD + i];
        int c = i / CHD, d = i - c * CHD;
        float nq = fmaxf(sqrtf(g_sumsq[bb * 384 + h * CHD + c]), 1e-12f);
        float nk = fmaxf(sqrtf(g_sumsq[bb * 384 + C1 + h * CHD + d]), 1e-12f);
        sA[i] = s / (nq * nk) * tpr;
    }
    __syncthreads();
    if (tid < CHD) {
        float mx = -1e30f;
        #pragma unroll
        for (int d = 0; d < CHD; d++) mx = fmaxf(mx, sA[tid * CHD + d]);
        float e[CHD];
        float ssum = 0.f;
        #pragma unroll
        for (int d = 0; d < CHD; d++) {
            e[d] = expf(sA[tid * CHD + d] - mx);
            ssum += e[d];
        }
        float inv = 1.f / ssum;
        #pragma unroll
        for (int d = 0; d < CHD; d++)
            g_attn[(size_t)bh * CHD * CHD + tid * CHD + d] = e[d] * inv;
    }
}

// ---------------- out = attn @ v  (per (b,h): 48x16384, K=48) ---------------
__global__ void __launch_bounds__(256) attnv_kernel(
    const float* __restrict__ qkv, float* __restrict__ out)
{
    const int bh = blockIdx.y;
    const int bb = bh >> 2, h = bh & 3;
    const int p = blockIdx.x * 256 + threadIdx.x;
    __shared__ float sA[CHD * CHD];
    for (int i = threadIdx.x; i < CHD * CHD; i += 256)
        sA[i] = g_attn[(size_t)bh * CHD * CHD + i];
    __syncthreads();
    const float* vb = qkv + ((size_t)bb * C3 + 2 * C1 + h * CHD) * NPIX + p;
    float vv[CHD];
    #pragma unroll
    for (int d = 0; d < CHD; d++) vv[d] = vb[(size_t)d * NPIX];
    float* ob = out + ((size_t)bb * C1 + h * CHD) * NPIX + p;
    for (int c = 0; c < CHD; c++) {
        float a = 0.f;
        #pragma unroll
        for (int d = 0; d < CHD; d++) a = fmaf(sA[c * CHD + d], vv[d], a);
        ob[(size_t)c * NPIX] = a;
    }
}

// ---------------- launch ----------------------------------------------------
extern "C" void kernel_launch(void* const* d_in, const int* in_sizes, int n_in,
                              void* d_out, int out_size)
{
    const float* x       = (const float*)d_in[0];
    const float* ln1_w   = (const float*)d_in[1];
    const float* ln1_b   = (const float*)d_in[2];
    const float* qkv_w   = (const float*)d_in[3];
    const float* qkv_b   = (const float*)d_in[4];
    const float* qkv_dww = (const float*)d_in[5];
    const float* qkv_dwb = (const float*)d_in[6];
    const float* temp    = (const float*)d_in[7];
    const float* prompt  = (const float*)d_in[8];
    const float* proj_w  = (const float*)d_in[9];
    const float* proj_b  = (const float*)d_in[10];
    const float* ln2_w   = (const float*)d_in[11];
    const float* ln2_b   = (const float*)d_in[12];
    const float* dw1_w   = (const float*)d_in[13];
    const float* dw1_b   = (const float*)d_in[14];
    const float* pm_w    = (const float*)d_in[15];
    const float* pm_b    = (const float*)d_in[16];
    const float* dw2_w   = (const float*)d_in[17];
    const float* dw2_b   = (const float*)d_in[18];
    const float* po_w    = (const float*)d_in[19];
    const float* po_b    = (const float*)d_in[20];
    float* out = (float*)d_out;

    void *pA, *pB, *pC, *pD;
    cudaGetSymbolAddress(&pA, g_bufA);
    cudaGetSymbolAddress(&pB, g_bufB);
    cudaGetSymbolAddress(&pC, g_bufC);
    cudaGetSymbolAddress(&pD, g_bufD);
    float* bufA = (float*)pA;
    float* bufB = (float*)pB;
    float* bufC = (float*)pC;
    float* bufD = (float*)pD;

    const int dwGrid = BATCH * C3 * NPIX / 256;

    // ---- attention branch ----
    ln_kernel<<<BATCH * NPIX / 256, 256>>>(x, bufC, ln1_w, ln1_b);
    gemm_tf32_kernel<0><<<dim3(NPIX / 256, C3 / 64, BATCH), 256>>>(
        bufC, bufA, qkv_w, qkv_b, nullptr, C3, C1);
    dwconv_kernel<1><<<dwGrid, 256>>>(bufA, bufB, qkv_dww, qkv_dwb, prompt);
    sumsq_kernel<<<BATCH * 384, 256>>>(bufB);
    qk_partial_kernel<<<dim3(32, 16), 256>>>(bufB);
    attn_softmax_kernel<<<32, 256>>>(temp);
    attnv_kernel<<<dim3(NPIX / 256, 32), 256>>>(bufB, bufC);
    gemm_tf32_kernel<2><<<dim3(NPIX / 256, C1 / 64, BATCH), 256>>>(
        bufC, bufD, proj_w, proj_b, x, C1, C1);       // y1 = x + proj(attn_out)

    // ---- FFN branch ----
    ln_kernel<<<BATCH * NPIX / 256, 256>>>(bufD, bufC, ln2_w, ln2_b);
    dwconv_kernel<3><<<dwGrid, 256>>>(bufC, bufA, dw1_w, dw1_b, nullptr);
    gemm_tf32_kernel<1><<<dim3(NPIX / 256, C3 / 64, BATCH), 256>>>(
        bufA, bufB, pm_w, pm_b, nullptr, C3, C3);     // + GELU
    dwconv_kernel<1><<<dwGrid, 256>>>(bufB, bufA, dw2_w, dw2_b, nullptr);
    gemm_tf32_kernel<2><<<dim3(NPIX / 256, C1 / 64, BATCH), 256>>>(
        bufA, out, po_w, po_b, bufD, C1, C3);         // out = y1 + po(...)
}

// round 7
// speedup vs baseline: 2.7059x; 1.6712x over previous
#include <cuda_runtime.h>
#include <math.h>
#include <stdint.h>

#define BATCH 8
#define C1    192
#define C3    576
#define HEADS 4
#define CHD   48
#define HH    128
#define WW    128
#define NPIX  16384
#define EPSV  1e-5f

// ---------------- scratch (static device allocations) -----------------------
__device__ float g_bufA[BATCH * C3 * NPIX];
__device__ float g_bufB[BATCH * C3 * NPIX];
__device__ float g_bufC[BATCH * C1 * NPIX];
__device__ float g_bufD[BATCH * C1 * NPIX];
__device__ float g_sumsq[BATCH * 2 * C1];
__device__ float g_attn_part[32 * 16 * CHD * CHD];
__device__ float g_attn[32 * CHD * CHD];
__device__ float g_M[BATCH * C1 * C1];        // fused proj_w @ blockdiag(attn)

// ---------------- LayerNorm over channel dim (per pixel) --------------------
__global__ void __launch_bounds__(256) ln_kernel(
    const float* __restrict__ x, float* __restrict__ out,
    const float* __restrict__ w, const float* __restrict__ b)
{
    int idx = blockIdx.x * 256 + threadIdx.x;
    int bb = idx >> 14;
    int p  = idx & (NPIX - 1);
    const float* xp = x + (size_t)bb * C1 * NPIX + p;
    float s = 0.f, s2 = 0.f;
    #pragma unroll 4
    for (int c = 0; c < C1; c++) {
        float v = xp[(size_t)c * NPIX];
        s += v; s2 = fmaf(v, v, s2);
    }
    float mu  = s * (1.f / C1);
    float var = fmaxf(s2 * (1.f / C1) - mu * mu, 0.f);
    float inv = rsqrtf(var + EPSV);
    float* op = out + (size_t)bb * C1 * NPIX + p;
    #pragma unroll 4
    for (int c = 0; c < C1; c++) {
        op[(size_t)c * NPIX] = (xp[(size_t)c * NPIX] - mu) * inv * w[c] + b[c];
    }
}

// ---------------- tf32 tensor-core GEMM with cp.async double buffering ------
// out[oc,p] = sum_ic W[oc,ic] * in[ic,p] (+bias, +fuse)
// FUSE: 0 = bias, 1 = bias+GELU(exact), 2 = bias+residual
// CTA 64(M) x 256(N), BK=32, 2-stage cp.async pipeline, dynamic smem.
#define ASTRIDE 36
#define BSTRIDE 264
#define ASTAGE  (64 * ASTRIDE)     // floats
#define BSTAGE  (32 * BSTRIDE)
#define GEMM_SMEM ((2 * (ASTAGE + BSTAGE)) * 4)

__device__ __forceinline__ void mma_tf32(float* c, const uint32_t* a, const uint32_t* b) {
    asm volatile(
        "mma.sync.aligned.m16n8k8.row.col.f32.tf32.tf32.f32 "
        "{%0,%1,%2,%3}, {%4,%5,%6,%7}, {%8,%9}, {%0,%1,%2,%3};\n"
        : "+f"(c[0]), "+f"(c[1]), "+f"(c[2]), "+f"(c[3])
        : "r"(a[0]), "r"(a[1]), "r"(a[2]), "r"(a[3]), "r"(b[0]), "r"(b[1]));
}
__device__ __forceinline__ void cp16(void* s, const void* g) {
    uint32_t sa = (uint32_t)__cvta_generic_to_shared(s);
    asm volatile("cp.async.cg.shared.global [%0], [%1], 16;\n" :: "r"(sa), "l"(g));
}

template<int FUSE>
__global__ void __launch_bounds__(256) gemm_tf32_kernel(
    const float* __restrict__ in, float* __restrict__ out,
    const float* __restrict__ W, const float* __restrict__ bias,
    const float* __restrict__ resid, int M, int K,
    int in_bstride, int in_coff, int w_bstride)
{
    extern __shared__ float dsm[];
    float* As = dsm;                  // [2][64][36]
    float* Bs = dsm + 2 * ASTAGE;     // [2][32][264]

    const int tid  = threadIdx.x;
    const int lane = tid & 31;
    const int wrp  = tid >> 5;
    const int n0   = blockIdx.x * 256;
    const int m0   = blockIdx.y * 64;
    const int bb   = blockIdx.z;
    const float* inb = in + ((size_t)bb * in_bstride + in_coff) * NPIX + n0;
    const float* Wb  = W + (size_t)bb * w_bstride;

    const int am = tid >> 2;          // A row 0..63
    const int ak = (tid & 3) * 8;     // A k base

    float acc[4][4][4];
    #pragma unroll
    for (int mt = 0; mt < 4; mt++)
        #pragma unroll
        for (int nt = 0; nt < 4; nt++)
            #pragma unroll
            for (int i = 0; i < 4; i++) acc[mt][nt][i] = 0.f;

    // stage loader
    auto load_stage = [&](int k0, int st) {
        const float* wr = Wb + (size_t)(m0 + am) * K + k0 + ak;
        float* ad = As + st * ASTAGE + am * ASTRIDE + ak;
        cp16(ad, wr);
        cp16(ad + 4, wr + 4);
        #pragma unroll
        for (int i = 0; i < 8; i++) {
            int l  = tid + i * 256;
            int r  = l >> 6;
            int c4 = (l & 63) * 4;
            cp16(Bs + st * BSTAGE + r * BSTRIDE + c4,
                 inb + (size_t)(k0 + r) * NPIX + c4);
        }
    };

    load_stage(0, 0);
    asm volatile("cp.async.commit_group;\n" ::);

    for (int k0 = 0; k0 < K; k0 += 32) {
        int st = (k0 >> 5) & 1;
        if (k0 + 32 < K) {
            load_stage(k0 + 32, st ^ 1);
            asm volatile("cp.async.commit_group;\n" ::);
            asm volatile("cp.async.wait_group 1;\n" ::);
        } else {
            asm volatile("cp.async.wait_all;\n" ::);
        }
        __syncthreads();

        const uint32_t* Au = (const uint32_t*)(As + st * ASTAGE);
        const uint32_t* Bu = (const uint32_t*)(Bs + st * BSTAGE);
        #pragma unroll
        for (int kk = 0; kk < 32; kk += 8) {
            const int kr   = kk + (lane & 3);
            const int mrow = lane >> 2;
            uint32_t a[4][4], b[4][2];
            #pragma unroll
            for (int mt = 0; mt < 4; mt++) {
                int mb = mt * 16 + mrow;
                a[mt][0] = Au[mb * ASTRIDE + kr];
                a[mt][1] = Au[(mb + 8) * ASTRIDE + kr];
                a[mt][2] = Au[mb * ASTRIDE + kr + 4];
                a[mt][3] = Au[(mb + 8) * ASTRIDE + kr + 4];
            }
            #pragma unroll
            for (int nt = 0; nt < 4; nt++) {
                int nc = wrp * 32 + nt * 8 + (lane >> 2);
                b[nt][0] = Bu[kr * BSTRIDE + nc];
                b[nt][1] = Bu[(kr + 4) * BSTRIDE + nc];
            }
            #pragma unroll
            for (int mt = 0; mt < 4; mt++)
                #pragma unroll
                for (int nt = 0; nt < 4; nt++)
                    mma_tf32(acc[mt][nt], a[mt], b[nt]);
        }
        __syncthreads();
    }

    // epilogue
    #pragma unroll
    for (int mt = 0; mt < 4; mt++) {
        int r0 = m0 + mt * 16 + (lane >> 2);
        int r1 = r0 + 8;
        float bv0 = __ldg(&bias[r0]);
        float bv1 = __ldg(&bias[r1]);
        float* o0 = out + ((size_t)bb * M + r0) * NPIX + n0;
        float* o1 = out + ((size_t)bb * M + r1) * NPIX + n0;
        #pragma unroll
        for (int nt = 0; nt < 4; nt++) {
            int col = wrp * 32 + nt * 8 + (lane & 3) * 2;
            float v0 = acc[mt][nt][0] + bv0;
            float v1 = acc[mt][nt][1] + bv0;
            float v2 = acc[mt][nt][2] + bv1;
            float v3 = acc[mt][nt][3] + bv1;
            if (FUSE == 1) {
                v0 = 0.5f * v0 * (1.f + erff(v0 * 0.70710678118654752f));
                v1 = 0.5f * v1 * (1.f + erff(v1 * 0.70710678118654752f));
                v2 = 0.5f * v2 * (1.f + erff(v2 * 0.70710678118654752f));
                v3 = 0.5f * v3 * (1.f + erff(v3 * 0.70710678118654752f));
            }
            if (FUSE == 2) {
                const float* rr0 = resid + ((size_t)bb * M + r0) * NPIX + n0;
                const float* rr1 = resid + ((size_t)bb * M + r1) * NPIX + n0;
                float2 q0 = *(const float2*)(rr0 + col);
                float2 q1 = *(const float2*)(rr1 + col);
                v0 += q0.x; v1 += q0.y; v2 += q1.x; v3 += q1.y;
            }
            *(float2*)(o0 + col) = make_float2(v0, v1);
            *(float2*)(o1 + col) = make_float2(v2, v3);
        }
    }
}

// ---------------- depthwise / grouped 3x3 conv, pad 1, 4 px/thread ----------
template<int RATIO, bool SUMSQ>
__global__ void __launch_bounds__(256) dwconv_kernel(
    const float* __restrict__ in, float* __restrict__ out,
    const float* __restrict__ wt, const float* __restrict__ bias,
    const float* __restrict__ prompt)
{
    int idx  = blockIdx.x * 256 + threadIdx.x;   // over BATCH*C3*NPIX/4
    int q    = idx & 4095;
    int rest = idx >> 12;
    int c    = rest % C3;
    int bb   = rest / C3;
    int p  = q << 2;
    int y  = p >> 7, x0 = p & 127;

    const float* ip = in + ((size_t)bb * (C3 / RATIO) + c / RATIO) * NPIX;
    const float* wp = wt + c * 9;
    float w[9];
    #pragma unroll
    for (int i = 0; i < 9; i++) w[i] = __ldg(&wp[i]);

    float bv = bias[c];
    if (prompt != nullptr)
        bv += prompt[((c % C1) / CHD) * CHD + (c % CHD)];
    float o0 = bv, o1 = bv, o2 = bv, o3 = bv;

    #pragma unroll
    for (int dy = -1; dy <= 1; dy++) {
        int yy = y + dy;
        if ((unsigned)yy < (unsigned)HH) {
            const float* rp = ip + yy * WW;
            float4 m = *(const float4*)(rp + x0);
            float L = (x0 > 0)   ? rp[x0 - 1] : 0.f;
            float R = (x0 < 124) ? rp[x0 + 4] : 0.f;
            float w0 = w[(dy + 1) * 3 + 0];
            float w1 = w[(dy + 1) * 3 + 1];
            float w2 = w[(dy + 1) * 3 + 2];
            o0 = fmaf(w0, L,   fmaf(w1, m.x, fmaf(w2, m.y, o0)));
            o1 = fmaf(w0, m.x, fmaf(w1, m.y, fmaf(w2, m.z, o1)));
            o2 = fmaf(w0, m.y, fmaf(w1, m.z, fmaf(w2, m.w, o2)));
            o3 = fmaf(w0, m.z, fmaf(w1, m.w, fmaf(w2, R,   o3)));
        }
    }
    *(float4*)(out + ((size_t)bb * C3 + c) * NPIX + p) = make_float4(o0, o1, o2, o3);

    if (SUMSQ) {
        // block is entirely within one channel; q/k channels are c < 384
        float ssq = o0 * o0 + o1 * o1 + o2 * o2 + o3 * o3;
        __shared__ float red[8];
        #pragma unroll
        for (int off = 16; off > 0; off >>= 1)
            ssq += __shfl_down_sync(0xffffffffu, ssq, off);
        if ((threadIdx.x & 31) == 0) red[threadIdx.x >> 5] = ssq;
        __syncthreads();
        if (threadIdx.x == 0 && c < 2 * C1) {
            float t = 0.f;
            #pragma unroll
            for (int wv = 0; wv < 8; wv++) t += red[wv];
            atomicAdd(&g_sumsq[bb * 2 * C1 + c], t);
        }
    }
}

// ---------------- QK^T partial GEMM (48x48, split-K over spatial) -----------
__global__ void __launch_bounds__(256) qk_partial_kernel(const float* __restrict__ qkv)
{
    const int bh = blockIdx.x, split = blockIdx.y;
    const int bb = bh >> 2, h = bh & 3;
    const float* qb = qkv + ((size_t)bb * C3 + h * CHD) * NPIX + split * 1024;
    const float* kb = qkv + ((size_t)bb * C3 + C1 + h * CHD) * NPIX + split * 1024;
    __shared__ float sq[CHD][33];
    __shared__ float sk[CHD][33];
    const int tid = threadIdx.x;
    const int c0 = (tid >> 4) * 3, d0 = (tid & 15) * 3;
    float acc[3][3] = {};

    for (int n0 = 0; n0 < 1024; n0 += 32) {
        for (int i = tid; i < CHD * 32; i += 256) {
            int c = i >> 5, j = i & 31;
            sq[c][j] = qb[(size_t)c * NPIX + n0 + j];
            sk[c][j] = kb[(size_t)c * NPIX + n0 + j];
        }
        __syncthreads();
        #pragma unroll
        for (int j = 0; j < 32; j++) {
            float q0 = sq[c0][j], q1 = sq[c0 + 1][j], q2 = sq[c0 + 2][j];
            float k0v = sk[d0][j], k1v = sk[d0 + 1][j], k2v = sk[d0 + 2][j];
            acc[0][0] = fmaf(q0, k0v, acc[0][0]);
            acc[0][1] = fmaf(q0, k1v, acc[0][1]);
            acc[0][2] = fmaf(q0, k2v, acc[0][2]);
            acc[1][0] = fmaf(q1, k0v, acc[1][0]);
            acc[1][1] = fmaf(q1, k1v, acc[1][1]);
            acc[1][2] = fmaf(q1, k2v, acc[1][2]);
            acc[2][0] = fmaf(q2, k0v, acc[2][0]);
            acc[2][1] = fmaf(q2, k1v, acc[2][1]);
            acc[2][2] = fmaf(q2, k2v, acc[2][2]);
        }
        __syncthreads();
    }
    float* op = g_attn_part + ((size_t)bh * 16 + split) * CHD * CHD;
    #pragma unroll
    for (int a = 0; a < 3; a++)
        #pragma unroll
        for (int e = 0; e < 3; e++)
            op[(c0 + a) * CHD + d0 + e] = acc[a][e];
}

// ---------------- reduce partials + normalize + temperature + softmax -------
__global__ void __launch_bounds__(256) attn_softmax_kernel(const float* __restrict__ temp)
{
    const int bh = blockIdx.x;
    const int bb = bh >> 2, h = bh & 3;
    __shared__ float sA[CHD * CHD];
    const int tid = threadIdx.x;
    const float tpr = temp[h];
    for (int i = tid; i < CHD * CHD; i += 256) {
        float s = 0.f;
        #pragma unroll
        for (int sp = 0; sp < 16; sp++)
            s += g_attn_part[((size_t)bh * 16 + sp) * CHD * CHD + i];
        int c = i / CHD, d = i - c * CHD;
        float nq = fmaxf(sqrtf(g_sumsq[bb * 384 + h * CHD + c]), 1e-12f);
        float nk = fmaxf(sqrtf(g_sumsq[bb * 384 + C1 + h * CHD + d]), 1e-12f);
        sA[i] = s / (nq * nk) * tpr;
    }
    __syncthreads();
    if (tid < CHD) {
        float mx = -1e30f;
        #pragma unroll
        for (int d = 0; d < CHD; d++) mx = fmaxf(mx, sA[tid * CHD + d]);
        float e[CHD];
        float ssum = 0.f;
        #pragma unroll
        for (int d = 0; d < CHD; d++) {
            e[d] = expf(sA[tid * CHD + d] - mx);
            ssum += e[d];
        }
        float inv = 1.f / ssum;
        #pragma unroll
        for (int d = 0; d < CHD; d++)
            g_attn[(size_t)bh * CHD * CHD + tid * CHD + d] = e[d] * inv;
    }
}

// ---------------- M[b] = proj_w @ blockdiag(attn[b]) ------------------------
__global__ void __launch_bounds__(256) buildM_kernel(const float* __restrict__ pw)
{
    int idx = blockIdx.x * 256 + threadIdx.x;   // 8*192*192
    int ci = idx % C1;
    int rest = idx / C1;
    int oc = rest % C1;
    int bb = rest / C1;
    int h = ci / CHD, d = ci % CHD;
    const float* a = g_attn + ((size_t)(bb * 4 + h)) * CHD * CHD + d;  // attn[cc][d]
    const float* w = pw + (size_t)oc * C1 + h * CHD;
    float s = 0.f;
    #pragma unroll
    for (int cc = 0; cc < CHD; cc++)
        s = fmaf(w[cc], a[(size_t)cc * CHD], s);
    g_M[((size_t)bb * C1 + oc) * C1 + ci] = s;
}

// ---------------- launch ----------------------------------------------------
extern "C" void kernel_launch(void* const* d_in, const int* in_sizes, int n_in,
                              void* d_out, int out_size)
{
    const float* x       = (const float*)d_in[0];
    const float* ln1_w   = (const float*)d_in[1];
    const float* ln1_b   = (const float*)d_in[2];
    const float* qkv_w   = (const float*)d_in[3];
    const float* qkv_b   = (const float*)d_in[4];
    const float* qkv_dww = (const float*)d_in[5];
    const float* qkv_dwb = (const float*)d_in[6];
    const float* temp    = (const float*)d_in[7];
    const float* prompt  = (const float*)d_in[8];
    const float* proj_w  = (const float*)d_in[9];
    const float* proj_b  = (const float*)d_in[10];
    const float* ln2_w   = (const float*)d_in[11];
    const float* ln2_b   = (const float*)d_in[12];
    const float* dw1_w   = (const float*)d_in[13];
    const float* dw1_b   = (const float*)d_in[14];
    const float* pm_w    = (const float*)d_in[15];
    const float* pm_b    = (const float*)d_in[16];
    const float* dw2_w   = (const float*)d_in[17];
    const float* dw2_b   = (const float*)d_in[18];
    const float* po_w    = (const float*)d_in[19];
    const float* po_b    = (const float*)d_in[20];
    float* out = (float*)d_out;

    void *pA, *pB, *pC, *pD, *pS, *pM;
    cudaGetSymbolAddress(&pA, g_bufA);
    cudaGetSymbolAddress(&pB, g_bufB);
    cudaGetSymbolAddress(&pC, g_bufC);
    cudaGetSymbolAddress(&pD, g_bufD);
    cudaGetSymbolAddress(&pS, g_sumsq);
    cudaGetSymbolAddress(&pM, g_M);
    float* bufA = (float*)pA;
    float* bufB = (float*)pB;
    float* bufC = (float*)pC;
    float* bufD = (float*)pD;
    float* Mptr = (float*)pM;

    cudaFuncSetAttribute(gemm_tf32_kernel<0>, cudaFuncAttributeMaxDynamicSharedMemorySize, GEMM_SMEM);
    cudaFuncSetAttribute(gemm_tf32_kernel<1>, cudaFuncAttributeMaxDynamicSharedMemorySize, GEMM_SMEM);
    cudaFuncSetAttribute(gemm_tf32_kernel<2>, cudaFuncAttributeMaxDynamicSharedMemorySize, GEMM_SMEM);

    const int dwGrid = BATCH * C3 * (NPIX / 4) / 256;   // 73728

    // ---- attention branch ----
    ln_kernel<<<BATCH * NPIX / 256, 256>>>(x, bufC, ln1_w, ln1_b);
    gemm_tf32_kernel<0><<<dim3(NPIX / 256, C3 / 64, BATCH), 256, GEMM_SMEM>>>(
        bufC, bufA, qkv_w, qkv_b, nullptr, C3, C1, C1, 0, 0);
    cudaMemsetAsync(pS, 0, BATCH * 2 * C1 * sizeof(float));
    dwconv_kernel<1, true><<<dwGrid, 256>>>(bufA, bufB, qkv_dww, qkv_dwb, prompt);
    qk_partial_kernel<<<dim3(32, 16), 256>>>(bufB);
    attn_softmax_kernel<<<32, 256>>>(temp);
    buildM_kernel<<<BATCH * C1 * C1 / 256, 256>>>(proj_w);
    // y1 = x + M @ v   (v = channels 384..575 of bufB)
    gemm_tf32_kernel<2><<<dim3(NPIX / 256, C1 / 64, BATCH), 256, GEMM_SMEM>>>(
        bufB, bufD, Mptr, proj_b, x, C1, C1, C3, 2 * C1, C1 * C1);

    // ---- FFN branch ----
    ln_kernel<<<BATCH * NPIX / 256, 256>>>(bufD, bufC, ln2_w, ln2_b);
    dwconv_kernel<3, false><<<dwGrid, 256>>>(bufC, bufA, dw1_w, dw1_b, nullptr);
    gemm_tf32_kernel<1><<<dim3(NPIX / 256, C3 / 64, BATCH), 256, GEMM_SMEM>>>(
        bufA, bufB, pm_w, pm_b, nullptr, C3, C3, C3, 0, 0);
    dwconv_kernel<1, false><<<dwGrid, 256>>>(bufB, bufA, dw2_w, dw2_b, nullptr);
    gemm_tf32_kernel<2><<<dim3(NPIX / 256, C1 / 64, BATCH), 256, GEMM_SMEM>>>(
        bufA, out, po_w, po_b, bufD, C1, C3, C3, 0, 0);
}